// round 9
// baseline (speedup 1.0000x reference)
#include <cuda_runtime.h>
#include <cuda_bf16.h>
#include <math.h>

#define NN 50000
#define NE 800000
#define DH 256
#define NC 40

// ---------------- device scratch (no allocations; referenced directly in device code) ----
__device__ int   g_cnt[NN];
__device__ int   g_ptr[NN + 1];
__device__ int   g_cur[NN];
__device__ int   g_srcs[NE];
__device__ float g_dis[NN];
__device__ float g_A[(size_t)NN * DH];    // GEMM out (layers 0,1)
__device__ float g_B[(size_t)NN * DH];    // aggregation out (layers 0,1)
__device__ float g_C40[(size_t)NN * NC];  // layer-2 GEMM out
__device__ float g_D40[(size_t)NN * NC];  // layer-2 aggregation out

// ---------------- CSR build (edge_index is int32: row 0 = src, row 1 = dst) ----------------
__global__ void zero_cnt_kernel() {
    int i = blockIdx.x * blockDim.x + threadIdx.x;
    if (i < NN) g_cnt[i] = 0;
}

__global__ void count_deg_kernel(const int* __restrict__ ei) {
    int e = blockIdx.x * blockDim.x + threadIdx.x;
    if (e < NE) {
        int d = ei[NE + e];
        if (d >= 0 && d < NN) atomicAdd(&g_cnt[d], 1);
    }
}

// single-block exclusive scan over g_cnt -> g_ptr / g_cur; g_dis = rsqrt(cnt+1)
__global__ __launch_bounds__(1024) void scan_kernel() {
    __shared__ int s[1024];
    int carry = 0;
    for (int base = 0; base < NN; base += 1024) {
        int i = base + threadIdx.x;
        int v = (i < NN) ? g_cnt[i] : 0;
        s[threadIdx.x] = v;
        __syncthreads();
#pragma unroll
        for (int off = 1; off < 1024; off <<= 1) {
            int t = (threadIdx.x >= off) ? s[threadIdx.x - off] : 0;
            __syncthreads();
            s[threadIdx.x] += t;
            __syncthreads();
        }
        int incl = s[threadIdx.x];
        int total = s[1023];
        int excl = incl - v;
        if (i < NN) {
            g_ptr[i] = carry + excl;
            g_cur[i] = carry + excl;
            g_dis[i] = rsqrtf((float)(v + 1));  // +1 self loop
        }
        carry += total;
        __syncthreads();
    }
    if (threadIdx.x == 0) g_ptr[NN] = carry;
}

__global__ void scatter_kernel(const int* __restrict__ ei) {
    int e = blockIdx.x * blockDim.x + threadIdx.x;
    if (e < NE) {
        int d = ei[NE + e];
        int srcv = ei[e];
        if (d >= 0 && d < NN && srcv >= 0 && srcv < NN) {
            int pos = atomicAdd(&g_cur[d], 1);
            g_srcs[pos] = srcv;
        }
    }
}

// ---------------- GEMM: C[M,N] = (relu?)A[M,K] @ W[K,N], K=256 ----------------
// in_sel: 0 -> A = xext (input), 1 -> A = g_B.  out_sel: 0 -> C = g_A, 1 -> C = g_C40.
__global__ __launch_bounds__(256)
void gemm_kernel(const float* __restrict__ xext, const float* __restrict__ W,
                 int M, int N, int relu_in, int in_sel, int out_sel) {
    const int K = DH;
    const float* A = (in_sel == 0) ? xext : (const float*)g_B;
    float* C = (out_sel == 0) ? (float*)g_A : (float*)g_C40;

    __shared__ float As[16][128];  // k-major
    __shared__ float Bs[16][128];  // k-major

    int tid = threadIdx.x;
    int bm = blockIdx.y * 128;
    int bn = blockIdx.x * 128;
    int tx = tid & 15;
    int ty = tid >> 4;

    float acc[8][8];
#pragma unroll
    for (int i = 0; i < 8; i++)
#pragma unroll
        for (int j = 0; j < 8; j++) acc[i][j] = 0.0f;

    for (int kt = 0; kt < K; kt += 16) {
#pragma unroll
        for (int l = 0; l < 2; l++) {
            int f = tid * 2 + l;            // 0..511
            int row = f >> 2;               // 0..127
            int kc = (f & 3) * 4;           // 0,4,8,12
            int grow = bm + row;
            float4 v = make_float4(0.f, 0.f, 0.f, 0.f);
            if (grow < M) v = *(const float4*)(A + (size_t)grow * K + kt + kc);
            if (relu_in) {
                v.x = fmaxf(v.x, 0.f); v.y = fmaxf(v.y, 0.f);
                v.z = fmaxf(v.z, 0.f); v.w = fmaxf(v.w, 0.f);
            }
            As[kc + 0][row] = v.x;
            As[kc + 1][row] = v.y;
            As[kc + 2][row] = v.z;
            As[kc + 3][row] = v.w;
        }
#pragma unroll
        for (int l = 0; l < 2; l++) {
            int f = tid * 2 + l;
            int kr = f >> 5;                // 0..15
            int col = (f & 31) * 4;         // 0..124
            int gc = bn + col;
            float4 v = make_float4(0.f, 0.f, 0.f, 0.f);
            if (gc + 3 < N) v = *(const float4*)(W + (size_t)(kt + kr) * N + gc);
            *(float4*)&Bs[kr][col] = v;
        }
        __syncthreads();

#pragma unroll
        for (int kk = 0; kk < 16; kk++) {
            float a[8], b[8];
            *(float4*)&a[0] = *(float4*)&As[kk][ty * 8];
            *(float4*)&a[4] = *(float4*)&As[kk][ty * 8 + 4];
            *(float4*)&b[0] = *(float4*)&Bs[kk][tx * 8];
            *(float4*)&b[4] = *(float4*)&Bs[kk][tx * 8 + 4];
#pragma unroll
            for (int i = 0; i < 8; i++)
#pragma unroll
                for (int j = 0; j < 8; j++) acc[i][j] += a[i] * b[j];
        }
        __syncthreads();
    }

#pragma unroll
    for (int i = 0; i < 8; i++) {
        int r = bm + ty * 8 + i;
        if (r >= M) continue;
#pragma unroll
        for (int j = 0; j < 8; j += 4) {
            int c = bn + tx * 8 + j;
            if (c + 3 < N) {
                float4 v = make_float4(acc[i][j], acc[i][j + 1], acc[i][j + 2], acc[i][j + 3]);
                *(float4*)(C + (size_t)r * N + c) = v;
            }
        }
    }
}

// ---------------- aggregation (gather): out[d] = b + dis[d]^2*xw[d] + sum dis[s]dis[d]*xw[s]
// one warp per node; DH=256: lane owns float4 slots {lane, lane+32}. xw = g_A, out = g_B.
__global__ __launch_bounds__(256)
void agg256_kernel(const float* __restrict__ bias) {
    const float* xw = (const float*)g_A;
    float* out = (float*)g_B;
    int node = blockIdx.x * (blockDim.x >> 5) + (threadIdx.x >> 5);
    int lane = threadIdx.x & 31;
    if (node >= NN) return;
    int beg = g_ptr[node], end = g_ptr[node + 1];
    float dd = g_dis[node];

    float4 acc0 = make_float4(0.f, 0.f, 0.f, 0.f);
    float4 acc1 = make_float4(0.f, 0.f, 0.f, 0.f);
    for (int i = beg; i < end; i++) {
        int s = g_srcs[i];
        float nrm = g_dis[s] * dd;
        const float4* row = (const float4*)(xw + (size_t)s * DH);
        float4 a = row[lane];
        float4 b = row[lane + 32];
        acc0.x += nrm * a.x; acc0.y += nrm * a.y; acc0.z += nrm * a.z; acc0.w += nrm * a.w;
        acc1.x += nrm * b.x; acc1.y += nrm * b.y; acc1.z += nrm * b.z; acc1.w += nrm * b.w;
    }
    {
        float self = dd * dd;
        const float4* row = (const float4*)(xw + (size_t)node * DH);
        float4 a = row[lane];
        float4 b = row[lane + 32];
        acc0.x += self * a.x; acc0.y += self * a.y; acc0.z += self * a.z; acc0.w += self * a.w;
        acc1.x += self * b.x; acc1.y += self * b.y; acc1.z += self * b.z; acc1.w += self * b.w;
    }
    const float4* bb = (const float4*)bias;
    float4 b0 = bb[lane], b1 = bb[lane + 32];
    acc0.x += b0.x; acc0.y += b0.y; acc0.z += b0.z; acc0.w += b0.w;
    acc1.x += b1.x; acc1.y += b1.y; acc1.z += b1.z; acc1.w += b1.w;
    float4* o = (float4*)(out + (size_t)node * DH);
    o[lane] = acc0;
    o[lane + 32] = acc1;
}

// NC=40: lane owns col lane, and col 32+lane for lanes 0..7. xw = g_C40, out = g_D40.
__global__ __launch_bounds__(256)
void agg40_kernel(const float* __restrict__ bias) {
    const float* xw = (const float*)g_C40;
    float* out = (float*)g_D40;
    int node = blockIdx.x * (blockDim.x >> 5) + (threadIdx.x >> 5);
    int lane = threadIdx.x & 31;
    if (node >= NN) return;
    int beg = g_ptr[node], end = g_ptr[node + 1];
    float dd = g_dis[node];
    bool hi = (lane < NC - 32);

    float a0 = 0.f, a1 = 0.f;
    for (int i = beg; i < end; i++) {
        int s = g_srcs[i];
        float nrm = g_dis[s] * dd;
        const float* row = xw + (size_t)s * NC;
        a0 += nrm * row[lane];
        if (hi) a1 += nrm * row[32 + lane];
    }
    {
        float self = dd * dd;
        const float* row = xw + (size_t)node * NC;
        a0 += self * row[lane];
        if (hi) a1 += self * row[32 + lane];
    }
    a0 += bias[lane];
    if (hi) a1 += bias[32 + lane];
    float* o = out + (size_t)node * NC;
    o[lane] = a0;
    if (hi) o[32 + lane] = a1;
}

// ---------------- log_softmax over 40 classes, one warp per row; input g_D40 ----------------
__global__ void log_softmax_kernel(float* __restrict__ out) {
    int row = blockIdx.x * (blockDim.x / 32) + (threadIdx.x >> 5);
    int lane = threadIdx.x & 31;
    if (row >= NN) return;
    const float* r = (const float*)g_D40 + (size_t)row * NC;
    float v0 = r[lane];
    float v1 = (lane < NC - 32) ? r[32 + lane] : -INFINITY;
    float mx = fmaxf(v0, v1);
#pragma unroll
    for (int o = 16; o > 0; o >>= 1) mx = fmaxf(mx, __shfl_xor_sync(0xFFFFFFFF, mx, o));
    float s = expf(v0 - mx) + ((lane < NC - 32) ? expf(v1 - mx) : 0.f);
#pragma unroll
    for (int o = 16; o > 0; o >>= 1) s += __shfl_xor_sync(0xFFFFFFFF, s, o);
    float lse = mx + logf(s);
    float* w = out + (size_t)row * NC;
    w[lane] = v0 - lse;
    if (lane < NC - 32) w[32 + lane] = v1 - lse;
}

// ---------------- launch ----------------
extern "C" void kernel_launch(void* const* d_in, const int* in_sizes, int n_in,
                              void* d_out, int out_size) {
    const float* x = (const float*)d_in[0];
    const int* ei = (const int*)d_in[1];   // int32! (JAX demotes int64 without x64)
    const float* W0 = (const float*)d_in[2];
    const float* b0 = (const float*)d_in[3];
    const float* W1 = (const float*)d_in[4];
    const float* b1 = (const float*)d_in[5];
    const float* W2 = (const float*)d_in[6];
    const float* b2 = (const float*)d_in[7];
    float* out = (float*)d_out;

    // CSR build + normalization
    zero_cnt_kernel<<<(NN + 255) / 256, 256>>>();
    count_deg_kernel<<<(NE + 255) / 256, 256>>>(ei);
    scan_kernel<<<1, 1024>>>();
    scatter_kernel<<<(NE + 255) / 256, 256>>>(ei);

    dim3 gemm_grid_big(DH / 128, (NN + 127) / 128);
    dim3 gemm_grid_small(1, (NN + 127) / 128);
    int agg_grid = (NN + 7) / 8;  // 8 warps per 256-thread block

    // ---- layer 0: A = x, C = g_A; agg g_A -> g_B ----
    gemm_kernel<<<gemm_grid_big, 256>>>(x, W0, NN, DH, 0, /*in_sel=*/0, /*out_sel=*/0);
    agg256_kernel<<<agg_grid, 256>>>(b0);

    // ---- layer 1: A = relu(g_B), C = g_A; agg g_A -> g_B ----
    gemm_kernel<<<gemm_grid_big, 256>>>(nullptr, W1, NN, DH, 1, /*in_sel=*/1, /*out_sel=*/0);
    agg256_kernel<<<agg_grid, 256>>>(b1);

    // ---- layer 2: A = relu(g_B), C = g_C40; agg g_C40 -> g_D40 ----
    gemm_kernel<<<gemm_grid_small, 256>>>(nullptr, W2, NN, NC, 1, /*in_sel=*/1, /*out_sel=*/1);
    agg40_kernel<<<agg_grid, 256>>>(b2);

    // ---- log_softmax: g_D40 -> out ----
    log_softmax_kernel<<<(NN * 32 + 255) / 256, 256>>>(out);
}